// round 14
// baseline (speedup 1.0000x reference)
#include <cuda_runtime.h>

#define KBINS 10000
#define MAXN  8400000
#define NB    592          // ranking chunks (4 blocks/SM)
#define FNT   256          // fused threads (8 warps; warp w owns keys with (k&7)==w)
#define FTILE 1024         // elements staged per tile
#define HNT   512
#define SCAN_ITEMS 10      // 1024 * 10 >= KBINS
#define BOT   ((NB + 31) / 32)   // blockoff scan tiles

// ------------------------- static device scratch (no allocs) ----------------
__device__ __align__(16) unsigned int   g_expg2[MAXN]; // packed (exp(lh), ev-bit) at desc pos
__device__ __align__(16) unsigned short g_H16[NB * KBINS]; // per-block histograms (u16)
__device__ int   g_O[NB * KBINS];    // per-block per-bin global asc start offsets
__device__ int   g_C[KBINS];         // total counts
__device__ int   g_Sarr[KBINS];      // exclusive prefix S[k]
__device__ int   g_off[KBINS];       // N - 2S - C   (pd = j + off)
__device__ float g_expg_sum[KBINS];
__device__ float g_ev_sum[KBINS];
__device__ float g_base[KBINS];
__device__ float g_totE;
__device__ double g_mse;

// FMA-pipe exp (rel err ~3e-6): 2^(x*log2e) with magic-number rounding.
__device__ __forceinline__ float fexp(float x) {
    float t  = x * 1.442695041f;
    float fn = t + 12582912.f;                 // round-to-nearest-even
    int   n  = __float_as_int(fn) - 0x4B400000;
    float f  = t - (fn - 12582912.f);          // f in [-0.5, 0.5]
    float p  = 1.33336e-3f;
    p = fmaf(p, f, 9.61812e-3f);
    p = fmaf(p, f, 5.55041e-2f);
    p = fmaf(p, f, 2.40226507e-1f);
    p = fmaf(p, f, 6.93147182e-1f);
    p = fmaf(p, f, 1.0f);
    return __int_as_float(__float_as_int(p) + (n << 23));
}

// ------------------------- kernels ------------------------------------------
__global__ void k_zero() {
    int i = blockIdx.x * blockDim.x + threadIdx.x;
    if (i < KBINS) g_C[i] = 0;
}

// per-block histogram over contiguous chunk (vectorized loads, u16 store)
// CH is a multiple of 4, so dur+start is int4-aligned.
__global__ void k_hist(const int* __restrict__ dur, int N, int CH) {
    __shared__ int sh[KBINS];
    for (int k = threadIdx.x; k < KBINS; k += HNT) sh[k] = 0;
    __syncthreads();
    int b = blockIdx.x;
    int start = b * CH, end = min(start + CH, N);
    int n = end - start;
    if (n > 0) {
        int nv = n >> 2;
        const int4* d4 = reinterpret_cast<const int4*>(dur + start);
        for (int g = threadIdx.x; g < nv; g += HNT) {
            int4 k4 = d4[g];
            atomicAdd(&sh[k4.x], 1); atomicAdd(&sh[k4.y], 1);
            atomicAdd(&sh[k4.z], 1); atomicAdd(&sh[k4.w], 1);
        }
        for (int i = start + (nv << 2) + threadIdx.x; i < end; i += HNT)
            atomicAdd(&sh[dur[i]], 1);
    }
    __syncthreads();
    for (int k = threadIdx.x; k < KBINS; k += HNT) {
        int c = sh[k];
        g_H16[b * KBINS + k] = (unsigned short)c;
        if (c) atomicAdd(&g_C[k], c);
    }
}

// exclusive scan of C -> S; off = N - 2S - C  (single block)
__global__ void k_scanC(int N) {
    __shared__ int s[1024];
    int tid = threadIdx.x;
    int loc[SCAN_ITEMS];
    int run = 0;
#pragma unroll
    for (int i = 0; i < SCAN_ITEMS; i++) {
        int k = tid * SCAN_ITEMS + i;
        int c = (k < KBINS) ? g_C[k] : 0;
        loc[i] = run;
        run += c;
    }
    s[tid] = run;
    __syncthreads();
    for (int o = 1; o < 1024; o <<= 1) {
        int v = (tid >= o) ? s[tid - o] : 0;
        __syncthreads();
        s[tid] += v;
        __syncthreads();
    }
    int excl = tid ? s[tid - 1] : 0;
#pragma unroll
    for (int i = 0; i < SCAN_ITEMS; i++) {
        int k = tid * SCAN_ITEMS + i;
        if (k < KBINS) {
            int S = excl + loc[i];
            g_Sarr[k] = S;
            g_off[k]  = N - 2 * S - g_C[k];
        }
    }
}

// O[b][k] = S[k] + sum_{b'<b} H[b'][k]
// Tiled transpose with one WARP per bin column (32 warps), staged through
// padded dynamic smem so global reads/writes are coalesced.
__global__ void __launch_bounds__(1024) k_blockoff() {
    extern __shared__ int tile[];   // NB * 33 ints
    int k0 = blockIdx.x * 32;
    for (int idx = threadIdx.x; idx < NB * 32; idx += 1024) {
        int b = idx >> 5, c = idx & 31;
        int k = k0 + c;
        tile[b * 33 + c] = (k < KBINS) ? (int)g_H16[b * KBINS + k] : 0;
    }
    __syncthreads();
    int c = threadIdx.x >> 5;        // warp id == column
    int lane = threadIdx.x & 31;
    int k = k0 + c;
    if (k < KBINS) {
        int carry = g_Sarr[k];
#pragma unroll
        for (int t = 0; t < BOT; t++) {
            int b = t * 32 + lane;
            int v = (b < NB) ? tile[b * 33 + c] : 0;
            int x = v;
#pragma unroll
            for (int o = 1; o < 32; o <<= 1) {
                int y = __shfl_up_sync(0xffffffffu, x, o);
                if (lane >= o) x += y;
            }
            if (b < NB) tile[b * 33 + c] = carry + x - v;  // exclusive + S
            carry += __shfl_sync(0xffffffffu, x, 31);
        }
    }
    __syncthreads();
    for (int idx = threadIdx.x; idx < NB * 32; idx += 1024) {
        int b = idx >> 5, c2 = idx & 31;
        int k2 = k0 + c2;
        if (k2 < KBINS) g_O[b * KBINS + k2] = tile[b * 33 + c2];
    }
}

// Fused stable-rank + scatter, barrier-light: per tile, all 8 warps stage
// 1024 (key, px) pairs into smem (coalesced, exp computed once); then each
// warp ranks only its owned keys ((key&7)==wid) from smem. Per-warp s_cnt
// regions are disjoint -> plain smem RMW by match leaders, no atomics, no
// cross-warp ordering. Stability: each warp walks groups in index order.
__global__ void __launch_bounds__(FNT, 4)
k_fused(const int* __restrict__ dur, const float* __restrict__ lh,
        const int* __restrict__ ev, int N, int CH) {
    __shared__ int      s_cnt[KBINS];   // running global asc positions
    __shared__ int      s_key[FTILE];
    __shared__ unsigned s_px[FTILE];
    int tid = threadIdx.x, wid = tid >> 5, lane = tid & 31;
    unsigned lt = (1u << lane) - 1u;
    int b = blockIdx.x;
    for (int k = tid; k < KBINS; k += FNT) s_cnt[k] = g_O[b * KBINS + k];
    __syncthreads();

    int start = b * CH, end = min(start + CH, N);
    for (int t0 = start; t0 < end; t0 += FTILE) {
        // ---- stage tile into smem (coalesced; exp computed once/elem) ----
#pragma unroll
        for (int m = 0; m < FTILE / FNT; m++) {
            int p = tid + m * FNT;
            int i = t0 + p;
            int key = 0x7fffffff;
            unsigned px = 0;
            if (i < end) {
                key = __ldg(dur + i);
                float e = fexp(__ldg(lh + i));
                px = (__float_as_uint(e) & 0xFFFFFFFEu) | (unsigned)(__ldg(ev + i) & 1);
            }
            s_key[p] = key;
            s_px[p]  = px;
        }
        __syncthreads();
        // ---- rank + scatter owned keys ----
#pragma unroll 4
        for (int g = 0; g < FTILE; g += 32) {
            int key = s_key[g + lane];
            unsigned ms = __match_any_sync(0xffffffffu, key);
            bool mine = (key < KBINS) && ((key & 7) == wid);
            if (mine) {
                int leader = __ffs(ms) - 1;
                int base = 0;
                if (lane == leader) {           // disjoint addrs across leaders
                    base = s_cnt[key];
                    s_cnt[key] = base + __popc(ms);
                }
                base = __shfl_sync(ms, base, leader);
                int j = base + __popc(ms & lt);
                int pd = j + __ldg(g_off + key);
                g_expg2[pd] = s_px[g + lane];
            }
        }
        __syncthreads();
    }
}

// Per-bin contiguous segment reduction over DESC ranges (no atomics):
// bin k occupies desc positions [N-S-C, N-S).
__global__ void k_segseg(int N) {
    int w = (blockIdx.x * blockDim.x + threadIdx.x) >> 5;
    int lane = threadIdx.x & 31;
    if (w >= KBINS) return;
    int S = g_Sarr[w], C = g_C[w];
    int p0 = N - S - C;
    float se = 0.f; int cv = 0;
    for (int r = lane; r < C; r += 32) {
        unsigned x = __ldg(g_expg2 + p0 + r);
        se += __uint_as_float(x & 0xFFFFFFFEu);
        cv += (int)(x & 1u);
    }
    for (int o = 16; o; o >>= 1) {
        se += __shfl_down_sync(0xffffffffu, se, o);
        cv += __shfl_down_sync(0xffffffffu, cv, o);
    }
    if (lane == 0) { g_expg_sum[w] = se; g_ev_sum[w] = (float)cv; }
}

// base[k] = ev_sum / reverse-cumsum(expg_sum); totE; reset mse
__global__ void k_base() {
    __shared__ float s[1024];
    __shared__ float s2[32];
    int tid = threadIdx.x;
    float loc[SCAN_ITEMS];
    float run = 0.f, evt = 0.f;
#pragma unroll
    for (int i = 0; i < SCAN_ITEMS; i++) {
        int m = tid * SCAN_ITEMS + i;
        int k = KBINS - 1 - m;
        float v = (k >= 0) ? g_expg_sum[k] : 0.f;
        if (k >= 0) evt += g_ev_sum[k];
        run += v;
        loc[i] = run;
    }
    s[tid] = run;
    __syncthreads();
    for (int o = 1; o < 1024; o <<= 1) {
        float v = (tid >= o) ? s[tid - o] : 0.f;
        __syncthreads();
        s[tid] += v;
        __syncthreads();
    }
    float excl = tid ? s[tid - 1] : 0.f;
#pragma unroll
    for (int i = 0; i < SCAN_ITEMS; i++) {
        int m = tid * SCAN_ITEMS + i;
        int k = KBINS - 1 - m;
        if (k >= 0) {
            float risk = excl + loc[i];
            g_base[k] = (risk > 0.f) ? (g_ev_sum[k] / risk) : 0.f;
        }
    }
    for (int o = 16; o; o >>= 1) evt += __shfl_down_sync(0xffffffffu, evt, o);
    if ((tid & 31) == 0) s2[tid >> 5] = evt;
    __syncthreads();
    if (tid < 32) {
        float v = s2[tid];
        for (int o = 16; o; o >>= 1) v += __shfl_down_sync(0xffffffffu, v, o);
        if (tid == 0) { g_totE = v; g_mse = 0.0; }
    }
}

// Per-bin MSE over contiguous ASC ranges: for asc rank j = S+r of bin k,
// term = base[k]*expval(expg2[j]) - ebit(expg2[j + off[k]]). Both streams
// are linear within the segment — no index arrays, no random gathers.
__global__ void k_mseseg(int N) {
    int w = (blockIdx.x * blockDim.x + threadIdx.x) >> 5;
    int lane = threadIdx.x & 31;
    __shared__ double sd[32];
    double wacc = 0.0;
    if (w < KBINS) {
        int S = g_Sarr[w], C = g_C[w], off = g_off[w];
        float bv = g_base[w];
        float acc = 0.f;
        for (int r = lane; r < C; r += 32) {
            unsigned qa = __ldg(g_expg2 + S + r);
            unsigned qb = __ldg(g_expg2 + S + r + off);
            float t = bv * __uint_as_float(qa & 0xFFFFFFFEu) - (float)(qb & 1u);
            acc += t * t;
        }
        wacc = (double)acc;
    }
    for (int o = 16; o; o >>= 1) wacc += __shfl_down_sync(0xffffffffu, wacc, o);
    int wl = threadIdx.x >> 5;
    if (lane == 0) sd[wl] = wacc;
    __syncthreads();
    if (threadIdx.x < 32) {
        int nw = blockDim.x >> 5;
        double v = (threadIdx.x < nw) ? sd[threadIdx.x] : 0.0;
        for (int o = 16; o; o >>= 1) v += __shfl_down_sync(0xffffffffu, v, o);
        if (threadIdx.x == 0) atomicAdd(&g_mse, v);
    }
}

__global__ void k_fin(float* out, int N) {
    out[0] = (g_totE == 0.f) ? 0.f : (float)(g_mse / (double)N);
}

// ------------------------- host launcher ------------------------------------
extern "C" void kernel_launch(void* const* d_in, const int* in_sizes, int n_in,
                              void* d_out, int out_size) {
    const float* lh  = (const float*)d_in[0];
    const int*   dur = (const int*)d_in[1];
    const int*   ev  = (const int*)d_in[2];
    int N = in_sizes[0];
    float* out = (float*)d_out;
    int CH = (((N + NB - 1) / NB) + 3) & ~3;   // multiple of 4 -> int4-aligned chunks

    size_t bo_smem = (size_t)NB * 33 * sizeof(int);
    cudaFuncSetAttribute(k_blockoff, cudaFuncAttributeMaxDynamicSharedMemorySize,
                         (int)bo_smem);

    k_zero<<<(KBINS + 1023) / 1024, 1024>>>();
    k_hist<<<NB, HNT>>>(dur, N, CH);
    k_scanC<<<1, 1024>>>(N);
    k_blockoff<<<(KBINS + 31) / 32, 1024, bo_smem>>>();
    k_fused<<<NB, FNT>>>(dur, lh, ev, N, CH);
    k_segseg<<<(KBINS * 32 + 255) / 256, 256>>>(N);
    k_base<<<1, 1024>>>();
    k_mseseg<<<(KBINS * 32 + 255) / 256, 256>>>(N);
    k_fin<<<1, 1>>>(out, N);
}

// round 15
// speedup vs baseline: 1.8746x; 1.8746x over previous
#include <cuda_runtime.h>

#define KBINS 10000
#define MAXN  8400000
#define NB    296          // ranking chunks (2 blocks/SM)
#define FNT   256          // fused threads (8 warps)
#define EPT   4            // match rounds per warp turn (128 elems/turn)
#define FTILE (FNT * EPT)  // 1024 elements per block-tile
#define HNT   512
#define SCAN_ITEMS 10      // 1024 * 10 >= KBINS
#define BOT   ((NB + 31) / 32)   // blockoff scan tiles

#define BAR_SYNC(id)   asm volatile("bar.sync %0, 64;"   :: "r"(id) : "memory")
#define BAR_ARRIVE(id) asm volatile("bar.arrive %0, 64;" :: "r"(id) : "memory")

// ------------------------- static device scratch (no allocs) ----------------
__device__ __align__(16) unsigned int   g_expg2[MAXN]; // packed (exp(lh), ev-bit) at desc pos
__device__ __align__(16) unsigned short g_H16[NB * KBINS]; // per-block histograms (u16)
__device__ int   g_O[NB * KBINS];    // per-block per-bin global asc start offsets
__device__ int   g_C[KBINS];         // total counts
__device__ int   g_Sarr[KBINS];      // exclusive prefix S[k]
__device__ int   g_off[KBINS];       // N - 2S - C   (pd = j + off)
__device__ float g_expg_sum[KBINS];
__device__ float g_ev_sum[KBINS];
__device__ float g_base[KBINS];
__device__ float g_totE;
__device__ double g_mse;

// ------------------------- kernels ------------------------------------------
__global__ void k_zero() {
    int i = blockIdx.x * blockDim.x + threadIdx.x;
    if (i < KBINS) g_C[i] = 0;
}

// per-block histogram over contiguous chunk (vectorized loads, u16 store)
// CH is a multiple of 4, so dur+start is int4-aligned.
__global__ void k_hist(const int* __restrict__ dur, int N, int CH) {
    __shared__ int sh[KBINS];
    for (int k = threadIdx.x; k < KBINS; k += HNT) sh[k] = 0;
    __syncthreads();
    int b = blockIdx.x;
    int start = b * CH, end = min(start + CH, N);
    int n = end - start;
    if (n > 0) {
        int nv = n >> 2;
        const int4* d4 = reinterpret_cast<const int4*>(dur + start);
        for (int g = threadIdx.x; g < nv; g += HNT) {
            int4 k4 = d4[g];
            atomicAdd(&sh[k4.x], 1); atomicAdd(&sh[k4.y], 1);
            atomicAdd(&sh[k4.z], 1); atomicAdd(&sh[k4.w], 1);
        }
        for (int i = start + (nv << 2) + threadIdx.x; i < end; i += HNT)
            atomicAdd(&sh[dur[i]], 1);
    }
    __syncthreads();
    for (int k = threadIdx.x; k < KBINS; k += HNT) {
        int c = sh[k];
        g_H16[b * KBINS + k] = (unsigned short)c;
        if (c) atomicAdd(&g_C[k], c);
    }
}

// exclusive scan of C -> S; off = N - 2S - C  (single block)
__global__ void k_scanC(int N) {
    __shared__ int s[1024];
    int tid = threadIdx.x;
    int loc[SCAN_ITEMS];
    int run = 0;
#pragma unroll
    for (int i = 0; i < SCAN_ITEMS; i++) {
        int k = tid * SCAN_ITEMS + i;
        int c = (k < KBINS) ? g_C[k] : 0;
        loc[i] = run;
        run += c;
    }
    s[tid] = run;
    __syncthreads();
    for (int o = 1; o < 1024; o <<= 1) {
        int v = (tid >= o) ? s[tid - o] : 0;
        __syncthreads();
        s[tid] += v;
        __syncthreads();
    }
    int excl = tid ? s[tid - 1] : 0;
#pragma unroll
    for (int i = 0; i < SCAN_ITEMS; i++) {
        int k = tid * SCAN_ITEMS + i;
        if (k < KBINS) {
            int S = excl + loc[i];
            g_Sarr[k] = S;
            g_off[k]  = N - 2 * S - g_C[k];
        }
    }
}

// O[b][k] = S[k] + sum_{b'<b} H[b'][k]
// Tiled transpose with one WARP per bin column (32 warps), staged through
// padded dynamic smem so global reads/writes are coalesced.
__global__ void __launch_bounds__(1024) k_blockoff() {
    extern __shared__ int tile[];   // NB * 33 ints
    int k0 = blockIdx.x * 32;
    for (int idx = threadIdx.x; idx < NB * 32; idx += 1024) {
        int b = idx >> 5, c = idx & 31;
        int k = k0 + c;
        tile[b * 33 + c] = (k < KBINS) ? (int)g_H16[b * KBINS + k] : 0;
    }
    __syncthreads();
    int c = threadIdx.x >> 5;        // warp id == column
    int lane = threadIdx.x & 31;
    int k = k0 + c;
    if (k < KBINS) {
        int carry = g_Sarr[k];
#pragma unroll
        for (int t = 0; t < BOT; t++) {
            int b = t * 32 + lane;
            int v = (b < NB) ? tile[b * 33 + c] : 0;
            int x = v;
#pragma unroll
            for (int o = 1; o < 32; o <<= 1) {
                int y = __shfl_up_sync(0xffffffffu, x, o);
                if (lane >= o) x += y;
            }
            if (b < NB) tile[b * 33 + c] = carry + x - v;  // exclusive + S
            carry += __shfl_sync(0xffffffffu, x, 31);
        }
    }
    __syncthreads();
    for (int idx = threadIdx.x; idx < NB * 32; idx += 1024) {
        int b = idx >> 5, c2 = idx & 31;
        int k2 = k0 + c2;
        if (k2 < KBINS) g_O[b * KBINS + k2] = tile[b * 33 + c2];
    }
}

// Fused stable-rank + scatter. Warps hand off via a named-barrier ring
// (producer bar.arrive -> consumer bar.sync). Ranking uses smem atomics
// (single active warp => stable). Only output: packed (exp(lh), ev-bit)
// scattered to the element's desc position.
__global__ void __launch_bounds__(FNT, 2)
k_fused(const int* __restrict__ dur, const float* __restrict__ lh,
        const int* __restrict__ ev, int N, int CH) {
    __shared__ int s_cnt[KBINS + 1];   // running global asc positions (+ sentinel)
    int tid = threadIdx.x, wid = tid >> 5, lane = tid & 31;
    unsigned lt = (1u << lane) - 1u;
    int b = blockIdx.x;
    for (int k = tid; k < KBINS; k += FNT) s_cnt[k] = g_O[b * KBINS + k];
    if (tid == 0) s_cnt[KBINS] = 0;
    __syncthreads();

    int start = b * CH, end = min(start + CH, N);
    int tl = 0;
    for (int t0 = start; t0 < end; t0 += FTILE, tl++) {
        int key[EPT]; unsigned px[EPT]; int idx0 = t0 + wid * (EPT * 32) + lane;
        // ---- prefetch + compute outside critical section ----
#pragma unroll
        for (int m = 0; m < EPT; m++) {
            int i = idx0 + m * 32;
            bool v = (i < end);
            key[m] = v ? dur[i] : KBINS;
            float lhv = v ? lh[i] : 0.f;
            int evv = v ? (ev[i] & 1) : 0;
            px[m] = (__float_as_uint(__expf(lhv)) & 0xFFFFFFFEu) | (unsigned)evv;
        }
        // ---- wait for our turn: turn g = tl*8 + wid ----
        int par = tl & 1;
        if (tl + wid > 0) BAR_SYNC(wid + 8 * par);
        // ---- serialized ranking (smem atomics, single active warp) ----
        int j[EPT];
#pragma unroll
        for (int m = 0; m < EPT; m++) {
            unsigned mask = __match_any_sync(0xffffffffu, key[m]);
            int leader = __ffs(mask) - 1;
            int base = 0;
            if (lane == leader) base = atomicAdd(&s_cnt[key[m]], __popc(mask));
            base = __shfl_sync(0xffffffffu, base, leader);
            j[m] = base + __popc(mask & lt);
        }
        // ---- hand off to next turn ----
        {
            int nw  = (wid + 1) & 7;
            int ntl = tl + (wid == 7);
            BAR_ARRIVE(nw + 8 * (ntl & 1));
        }
        // ---- scatter outside critical section ----
#pragma unroll
        for (int m = 0; m < EPT; m++) {
            if (key[m] < KBINS) {
                int pd = j[m] + __ldg(g_off + key[m]);
                g_expg2[pd] = px[m];
            }
        }
    }
}

// Per-bin contiguous segment reduction over DESC ranges (no atomics):
// bin k occupies desc positions [N-S-C, N-S).
__global__ void k_segseg(int N) {
    int w = (blockIdx.x * blockDim.x + threadIdx.x) >> 5;
    int lane = threadIdx.x & 31;
    if (w >= KBINS) return;
    int S = g_Sarr[w], C = g_C[w];
    int p0 = N - S - C;
    float se = 0.f; int cv = 0;
    for (int r = lane; r < C; r += 32) {
        unsigned x = __ldg(g_expg2 + p0 + r);
        se += __uint_as_float(x & 0xFFFFFFFEu);
        cv += (int)(x & 1u);
    }
    for (int o = 16; o; o >>= 1) {
        se += __shfl_down_sync(0xffffffffu, se, o);
        cv += __shfl_down_sync(0xffffffffu, cv, o);
    }
    if (lane == 0) { g_expg_sum[w] = se; g_ev_sum[w] = (float)cv; }
}

// base[k] = ev_sum / reverse-cumsum(expg_sum); totE; reset mse
__global__ void k_base() {
    __shared__ float s[1024];
    __shared__ float s2[32];
    int tid = threadIdx.x;
    float loc[SCAN_ITEMS];
    float run = 0.f, evt = 0.f;
#pragma unroll
    for (int i = 0; i < SCAN_ITEMS; i++) {
        int m = tid * SCAN_ITEMS + i;
        int k = KBINS - 1 - m;
        float v = (k >= 0) ? g_expg_sum[k] : 0.f;
        if (k >= 0) evt += g_ev_sum[k];
        run += v;
        loc[i] = run;
    }
    s[tid] = run;
    __syncthreads();
    for (int o = 1; o < 1024; o <<= 1) {
        float v = (tid >= o) ? s[tid - o] : 0.f;
        __syncthreads();
        s[tid] += v;
        __syncthreads();
    }
    float excl = tid ? s[tid - 1] : 0.f;
#pragma unroll
    for (int i = 0; i < SCAN_ITEMS; i++) {
        int m = tid * SCAN_ITEMS + i;
        int k = KBINS - 1 - m;
        if (k >= 0) {
            float risk = excl + loc[i];
            g_base[k] = (risk > 0.f) ? (g_ev_sum[k] / risk) : 0.f;
        }
    }
    for (int o = 16; o; o >>= 1) evt += __shfl_down_sync(0xffffffffu, evt, o);
    if ((tid & 31) == 0) s2[tid >> 5] = evt;
    __syncthreads();
    if (tid < 32) {
        float v = s2[tid];
        for (int o = 16; o; o >>= 1) v += __shfl_down_sync(0xffffffffu, v, o);
        if (tid == 0) { g_totE = v; g_mse = 0.0; }
    }
}

// Per-bin MSE over contiguous ASC ranges: for asc rank j = S+r of bin k,
// term = base[k]*expval(expg2[j]) - ebit(expg2[j + off[k]]). Both streams
// are linear within the segment — no index arrays, no random gathers.
__global__ void k_mseseg(int N) {
    int w = (blockIdx.x * blockDim.x + threadIdx.x) >> 5;
    int lane = threadIdx.x & 31;
    __shared__ double sd[32];
    double wacc = 0.0;
    if (w < KBINS) {
        int S = g_Sarr[w], C = g_C[w], off = g_off[w];
        float bv = g_base[w];
        float acc = 0.f;
        for (int r = lane; r < C; r += 32) {
            unsigned qa = __ldg(g_expg2 + S + r);
            unsigned qb = __ldg(g_expg2 + S + r + off);
            float t = bv * __uint_as_float(qa & 0xFFFFFFFEu) - (float)(qb & 1u);
            acc += t * t;
        }
        wacc = (double)acc;
    }
    for (int o = 16; o; o >>= 1) wacc += __shfl_down_sync(0xffffffffu, wacc, o);
    int wl = threadIdx.x >> 5;
    if (lane == 0) sd[wl] = wacc;
    __syncthreads();
    if (threadIdx.x < 32) {
        int nw = blockDim.x >> 5;
        double v = (threadIdx.x < nw) ? sd[threadIdx.x] : 0.0;
        for (int o = 16; o; o >>= 1) v += __shfl_down_sync(0xffffffffu, v, o);
        if (threadIdx.x == 0) atomicAdd(&g_mse, v);
    }
}

__global__ void k_fin(float* out, int N) {
    out[0] = (g_totE == 0.f) ? 0.f : (float)(g_mse / (double)N);
}

// ------------------------- host launcher ------------------------------------
extern "C" void kernel_launch(void* const* d_in, const int* in_sizes, int n_in,
                              void* d_out, int out_size) {
    const float* lh  = (const float*)d_in[0];
    const int*   dur = (const int*)d_in[1];
    const int*   ev  = (const int*)d_in[2];
    int N = in_sizes[0];
    float* out = (float*)d_out;
    int CH = (((N + NB - 1) / NB) + 3) & ~3;   // multiple of 4 -> int4-aligned chunks

    size_t bo_smem = (size_t)NB * 33 * sizeof(int);
    cudaFuncSetAttribute(k_blockoff, cudaFuncAttributeMaxDynamicSharedMemorySize,
                         (int)bo_smem);

    k_zero<<<(KBINS + 1023) / 1024, 1024>>>();
    k_hist<<<NB, HNT>>>(dur, N, CH);
    k_scanC<<<1, 1024>>>(N);
    k_blockoff<<<(KBINS + 31) / 32, 1024, bo_smem>>>();
    k_fused<<<NB, FNT>>>(dur, lh, ev, N, CH);
    k_segseg<<<(KBINS * 32 + 255) / 256, 256>>>(N);
    k_base<<<1, 1024>>>();
    k_mseseg<<<(KBINS * 32 + 255) / 256, 256>>>(N);
    k_fin<<<1, 1>>>(out, N);
}

// round 16
// speedup vs baseline: 3.5665x; 1.9025x over previous
#include <cuda_runtime.h>

#define KBINS 10000
#define MAXN  8400000
#define NB    592          // ranking chunks (4 blocks/SM)
#define FNT   256          // fused threads (8 warps)
#define EPT   4            // match rounds per warp turn (128 elems/turn)
#define FTILE (FNT * EPT)  // 1024 elements per block-tile
#define HNT   512
#define SCAN_ITEMS 10      // 1024 * 10 >= KBINS
#define BOT   ((NB + 31) / 32)   // blockoff scan tiles

#define BAR_SYNC(id)   asm volatile("bar.sync %0, 64;"   :: "r"(id) : "memory")
#define BAR_ARRIVE(id) asm volatile("bar.arrive %0, 64;" :: "r"(id) : "memory")

// ------------------------- static device scratch (no allocs) ----------------
__device__ __align__(16) unsigned int   g_expg2[MAXN]; // packed (exp(lh), ev-bit) at desc pos
__device__ __align__(16) unsigned short g_H16[NB * KBINS]; // per-block histograms (u16)
__device__ int   g_O[NB * KBINS];    // per-block per-bin global asc start offsets
__device__ int   g_C[KBINS];         // total counts
__device__ int   g_Sarr[KBINS];      // exclusive prefix S[k]
__device__ int   g_off[KBINS];       // N - 2S - C   (pd = j + off)
__device__ float g_expg_sum[KBINS];
__device__ float g_ev_sum[KBINS];
__device__ float g_base[KBINS];
__device__ float g_totE;
__device__ double g_mse;

// ------------------------- kernels ------------------------------------------
__global__ void k_zero() {
    int i = blockIdx.x * blockDim.x + threadIdx.x;
    if (i < KBINS) g_C[i] = 0;
}

// per-block histogram over contiguous chunk (vectorized loads, u16 store)
// CH is a multiple of 4, so dur+start is int4-aligned.
__global__ void k_hist(const int* __restrict__ dur, int N, int CH) {
    __shared__ int sh[KBINS];
    for (int k = threadIdx.x; k < KBINS; k += HNT) sh[k] = 0;
    __syncthreads();
    int b = blockIdx.x;
    int start = b * CH, end = min(start + CH, N);
    int n = end - start;
    if (n > 0) {
        int nv = n >> 2;
        const int4* d4 = reinterpret_cast<const int4*>(dur + start);
        for (int g = threadIdx.x; g < nv; g += HNT) {
            int4 k4 = d4[g];
            atomicAdd(&sh[k4.x], 1); atomicAdd(&sh[k4.y], 1);
            atomicAdd(&sh[k4.z], 1); atomicAdd(&sh[k4.w], 1);
        }
        for (int i = start + (nv << 2) + threadIdx.x; i < end; i += HNT)
            atomicAdd(&sh[dur[i]], 1);
    }
    __syncthreads();
    for (int k = threadIdx.x; k < KBINS; k += HNT) {
        int c = sh[k];
        g_H16[b * KBINS + k] = (unsigned short)c;
        if (c) atomicAdd(&g_C[k], c);
    }
}

// exclusive scan of C -> S; off = N - 2S - C  (single block)
__global__ void k_scanC(int N) {
    __shared__ int s[1024];
    int tid = threadIdx.x;
    int loc[SCAN_ITEMS];
    int run = 0;
#pragma unroll
    for (int i = 0; i < SCAN_ITEMS; i++) {
        int k = tid * SCAN_ITEMS + i;
        int c = (k < KBINS) ? g_C[k] : 0;
        loc[i] = run;
        run += c;
    }
    s[tid] = run;
    __syncthreads();
    for (int o = 1; o < 1024; o <<= 1) {
        int v = (tid >= o) ? s[tid - o] : 0;
        __syncthreads();
        s[tid] += v;
        __syncthreads();
    }
    int excl = tid ? s[tid - 1] : 0;
#pragma unroll
    for (int i = 0; i < SCAN_ITEMS; i++) {
        int k = tid * SCAN_ITEMS + i;
        if (k < KBINS) {
            int S = excl + loc[i];
            g_Sarr[k] = S;
            g_off[k]  = N - 2 * S - g_C[k];
        }
    }
}

// O[b][k] = S[k] + sum_{b'<b} H[b'][k]
// Tiled transpose with one WARP per bin column (32 warps), staged through
// padded dynamic smem so global reads/writes are coalesced.
__global__ void __launch_bounds__(1024) k_blockoff() {
    extern __shared__ int tile[];   // NB * 33 ints
    int k0 = blockIdx.x * 32;
    for (int idx = threadIdx.x; idx < NB * 32; idx += 1024) {
        int b = idx >> 5, c = idx & 31;
        int k = k0 + c;
        tile[b * 33 + c] = (k < KBINS) ? (int)g_H16[b * KBINS + k] : 0;
    }
    __syncthreads();
    int c = threadIdx.x >> 5;        // warp id == column
    int lane = threadIdx.x & 31;
    int k = k0 + c;
    if (k < KBINS) {
        int carry = g_Sarr[k];
#pragma unroll
        for (int t = 0; t < BOT; t++) {
            int b = t * 32 + lane;
            int v = (b < NB) ? tile[b * 33 + c] : 0;
            int x = v;
#pragma unroll
            for (int o = 1; o < 32; o <<= 1) {
                int y = __shfl_up_sync(0xffffffffu, x, o);
                if (lane >= o) x += y;
            }
            if (b < NB) tile[b * 33 + c] = carry + x - v;  // exclusive + S
            carry += __shfl_sync(0xffffffffu, x, 31);
        }
    }
    __syncthreads();
    for (int idx = threadIdx.x; idx < NB * 32; idx += 1024) {
        int b = idx >> 5, c2 = idx & 31;
        int k2 = k0 + c2;
        if (k2 < KBINS) g_O[b * KBINS + k2] = tile[b * 33 + c2];
    }
}

// Fused stable-rank + scatter. Warps hand off via a named-barrier ring
// (producer bar.arrive -> consumer bar.sync). Single active warp in the
// critical section => plain LDS/STS RMW by match leaders (no atomics, no
// shfl broadcast: every lane reads s_cnt[key] itself — intra-group smem
// broadcast is free). Sequential rounds keep same-key correctness.
__global__ void __launch_bounds__(FNT, 2)
k_fused(const int* __restrict__ dur, const float* __restrict__ lh,
        const int* __restrict__ ev, int N, int CH) {
    __shared__ int s_cnt[KBINS + 1];   // running global asc positions (+ sentinel)
    int tid = threadIdx.x, wid = tid >> 5, lane = tid & 31;
    unsigned lt = (1u << lane) - 1u;
    int b = blockIdx.x;
    for (int k = tid; k < KBINS; k += FNT) s_cnt[k] = g_O[b * KBINS + k];
    if (tid == 0) s_cnt[KBINS] = 0;
    __syncthreads();

    int start = b * CH, end = min(start + CH, N);
    int tl = 0;
    for (int t0 = start; t0 < end; t0 += FTILE, tl++) {
        int key[EPT]; unsigned px[EPT]; int idx0 = t0 + wid * (EPT * 32) + lane;
        // ---- prefetch + compute outside critical section ----
#pragma unroll
        for (int m = 0; m < EPT; m++) {
            int i = idx0 + m * 32;
            bool v = (i < end);
            key[m] = v ? dur[i] : KBINS;
            float lhv = v ? lh[i] : 0.f;
            int evv = v ? (ev[i] & 1) : 0;
            px[m] = (__float_as_uint(__expf(lhv)) & 0xFFFFFFFEu) | (unsigned)evv;
        }
        // ---- wait for our turn: turn g = tl*8 + wid ----
        int par = tl & 1;
        if (tl + wid > 0) BAR_SYNC(wid + 8 * par);
        // ---- serialized ranking (plain smem RMW, single active warp) ----
        int j[EPT];
#pragma unroll
        for (int m = 0; m < EPT; m++) {
            unsigned mask = __match_any_sync(0xffffffffu, key[m]);
            int base = s_cnt[key[m]];                     // smem broadcast per group
            if (lane == (__ffs(mask) - 1))                // leader: distinct addr per group
                s_cnt[key[m]] = base + __popc(mask);
            j[m] = base + __popc(mask & lt);
        }
        // ---- hand off to next turn ----
        {
            int nw  = (wid + 1) & 7;
            int ntl = tl + (wid == 7);
            BAR_ARRIVE(nw + 8 * (ntl & 1));
        }
        // ---- scatter outside critical section ----
#pragma unroll
        for (int m = 0; m < EPT; m++) {
            if (key[m] < KBINS) {
                int pd = j[m] + __ldg(g_off + key[m]);
                g_expg2[pd] = px[m];
            }
        }
    }
}

// Per-bin contiguous segment reduction over DESC ranges (no atomics):
// bin k occupies desc positions [N-S-C, N-S).
__global__ void k_segseg(int N) {
    int w = (blockIdx.x * blockDim.x + threadIdx.x) >> 5;
    int lane = threadIdx.x & 31;
    if (w >= KBINS) return;
    int S = g_Sarr[w], C = g_C[w];
    int p0 = N - S - C;
    float se = 0.f; int cv = 0;
    for (int r = lane; r < C; r += 32) {
        unsigned x = __ldg(g_expg2 + p0 + r);
        se += __uint_as_float(x & 0xFFFFFFFEu);
        cv += (int)(x & 1u);
    }
    for (int o = 16; o; o >>= 1) {
        se += __shfl_down_sync(0xffffffffu, se, o);
        cv += __shfl_down_sync(0xffffffffu, cv, o);
    }
    if (lane == 0) { g_expg_sum[w] = se; g_ev_sum[w] = (float)cv; }
}

// base[k] = ev_sum / reverse-cumsum(expg_sum); totE; reset mse
__global__ void k_base() {
    __shared__ float s[1024];
    __shared__ float s2[32];
    int tid = threadIdx.x;
    float loc[SCAN_ITEMS];
    float run = 0.f, evt = 0.f;
#pragma unroll
    for (int i = 0; i < SCAN_ITEMS; i++) {
        int m = tid * SCAN_ITEMS + i;
        int k = KBINS - 1 - m;
        float v = (k >= 0) ? g_expg_sum[k] : 0.f;
        if (k >= 0) evt += g_ev_sum[k];
        run += v;
        loc[i] = run;
    }
    s[tid] = run;
    __syncthreads();
    for (int o = 1; o < 1024; o <<= 1) {
        float v = (tid >= o) ? s[tid - o] : 0.f;
        __syncthreads();
        s[tid] += v;
        __syncthreads();
    }
    float excl = tid ? s[tid - 1] : 0.f;
#pragma unroll
    for (int i = 0; i < SCAN_ITEMS; i++) {
        int m = tid * SCAN_ITEMS + i;
        int k = KBINS - 1 - m;
        if (k >= 0) {
            float risk = excl + loc[i];
            g_base[k] = (risk > 0.f) ? (g_ev_sum[k] / risk) : 0.f;
        }
    }
    for (int o = 16; o; o >>= 1) evt += __shfl_down_sync(0xffffffffu, evt, o);
    if ((tid & 31) == 0) s2[tid >> 5] = evt;
    __syncthreads();
    if (tid < 32) {
        float v = s2[tid];
        for (int o = 16; o; o >>= 1) v += __shfl_down_sync(0xffffffffu, v, o);
        if (tid == 0) { g_totE = v; g_mse = 0.0; }
    }
}

// Per-bin MSE over contiguous ASC ranges: for asc rank j = S+r of bin k,
// term = base[k]*expval(expg2[j]) - ebit(expg2[j + off[k]]). Both streams
// are linear within the segment — no index arrays, no random gathers.
__global__ void k_mseseg(int N) {
    int w = (blockIdx.x * blockDim.x + threadIdx.x) >> 5;
    int lane = threadIdx.x & 31;
    __shared__ double sd[32];
    double wacc = 0.0;
    if (w < KBINS) {
        int S = g_Sarr[w], C = g_C[w], off = g_off[w];
        float bv = g_base[w];
        float acc = 0.f;
        for (int r = lane; r < C; r += 32) {
            unsigned qa = __ldg(g_expg2 + S + r);
            unsigned qb = __ldg(g_expg2 + S + r + off);
            float t = bv * __uint_as_float(qa & 0xFFFFFFFEu) - (float)(qb & 1u);
            acc += t * t;
        }
        wacc = (double)acc;
    }
    for (int o = 16; o; o >>= 1) wacc += __shfl_down_sync(0xffffffffu, wacc, o);
    int wl = threadIdx.x >> 5;
    if (lane == 0) sd[wl] = wacc;
    __syncthreads();
    if (threadIdx.x < 32) {
        int nw = blockDim.x >> 5;
        double v = (threadIdx.x < nw) ? sd[threadIdx.x] : 0.0;
        for (int o = 16; o; o >>= 1) v += __shfl_down_sync(0xffffffffu, v, o);
        if (threadIdx.x == 0) atomicAdd(&g_mse, v);
    }
}

__global__ void k_fin(float* out, int N) {
    out[0] = (g_totE == 0.f) ? 0.f : (float)(g_mse / (double)N);
}

// ------------------------- host launcher ------------------------------------
extern "C" void kernel_launch(void* const* d_in, const int* in_sizes, int n_in,
                              void* d_out, int out_size) {
    const float* lh  = (const float*)d_in[0];
    const int*   dur = (const int*)d_in[1];
    const int*   ev  = (const int*)d_in[2];
    int N = in_sizes[0];
    float* out = (float*)d_out;
    int CH = (((N + NB - 1) / NB) + 3) & ~3;   // multiple of 4 -> int4-aligned chunks

    size_t bo_smem = (size_t)NB * 33 * sizeof(int);
    cudaFuncSetAttribute(k_blockoff, cudaFuncAttributeMaxDynamicSharedMemorySize,
                         (int)bo_smem);

    k_zero<<<(KBINS + 1023) / 1024, 1024>>>();
    k_hist<<<NB, HNT>>>(dur, N, CH);
    k_scanC<<<1, 1024>>>(N);
    k_blockoff<<<(KBINS + 31) / 32, 1024, bo_smem>>>();
    k_fused<<<NB, FNT>>>(dur, lh, ev, N, CH);
    k_segseg<<<(KBINS * 32 + 255) / 256, 256>>>(N);
    k_base<<<1, 1024>>>();
    k_mseseg<<<(KBINS * 32 + 255) / 256, 256>>>(N);
    k_fin<<<1, 1>>>(out, N);
}

// round 17
// speedup vs baseline: 3.9063x; 1.0953x over previous
#include <cuda_runtime.h>

#define KBINS 10000
#define MAXN  8400000
#define NB    592          // ranking chunks (4 blocks/SM)
#define GRP   4            // blocks per offset group
#define NBG   (NB / GRP)   // 148 offset groups
#define FNT   256          // fused threads (8 warps)
#define EPT   4            // match rounds per warp turn (128 elems/turn)
#define FTILE (FNT * EPT)  // 1024 elements per block-tile
#define HNT   512
#define SCAN_ITEMS 10      // 1024 * 10 >= KBINS
#define BOT   ((NBG + 31) / 32)  // blockoff scan tiles (per-group)

#define BAR_SYNC(id)   asm volatile("bar.sync %0, 64;"   :: "r"(id) : "memory")
#define BAR_ARRIVE(id) asm volatile("bar.arrive %0, 64;" :: "r"(id) : "memory")

// ------------------------- static device scratch (no allocs) ----------------
__device__ __align__(16) unsigned int   g_expg2[MAXN]; // packed (exp(lh), ev-bit) at desc pos
__device__ __align__(16) unsigned short g_H16[NB * KBINS]; // per-block histograms (u16)
__device__ int   g_O[NBG * KBINS];   // per-GROUP per-bin global asc start offsets
__device__ int   g_C[KBINS];         // total counts
__device__ int   g_Sarr[KBINS];      // exclusive prefix S[k]
__device__ int   g_off[KBINS];       // N - 2S - C   (pd = j + off)
__device__ float g_expg_sum[KBINS];
__device__ float g_ev_sum[KBINS];
__device__ float g_base[KBINS];
__device__ float g_totE;
__device__ double g_mse;

// ------------------------- kernels ------------------------------------------
__global__ void k_zero() {
    int i = blockIdx.x * blockDim.x + threadIdx.x;
    if (i < KBINS) g_C[i] = 0;
}

// per-block histogram over contiguous chunk (vectorized loads, u16 store)
// CH is a multiple of 4, so dur+start is int4-aligned.
__global__ void k_hist(const int* __restrict__ dur, int N, int CH) {
    __shared__ int sh[KBINS];
    for (int k = threadIdx.x; k < KBINS; k += HNT) sh[k] = 0;
    __syncthreads();
    int b = blockIdx.x;
    int start = b * CH, end = min(start + CH, N);
    int n = end - start;
    if (n > 0) {
        int nv = n >> 2;
        const int4* d4 = reinterpret_cast<const int4*>(dur + start);
        for (int g = threadIdx.x; g < nv; g += HNT) {
            int4 k4 = d4[g];
            atomicAdd(&sh[k4.x], 1); atomicAdd(&sh[k4.y], 1);
            atomicAdd(&sh[k4.z], 1); atomicAdd(&sh[k4.w], 1);
        }
        for (int i = start + (nv << 2) + threadIdx.x; i < end; i += HNT)
            atomicAdd(&sh[dur[i]], 1);
    }
    __syncthreads();
    for (int k = threadIdx.x; k < KBINS; k += HNT) {
        int c = sh[k];
        g_H16[b * KBINS + k] = (unsigned short)c;
        if (c) atomicAdd(&g_C[k], c);
    }
}

// exclusive scan of C -> S; off = N - 2S - C  (single block)
__global__ void k_scanC(int N) {
    __shared__ int s[1024];
    int tid = threadIdx.x;
    int loc[SCAN_ITEMS];
    int run = 0;
#pragma unroll
    for (int i = 0; i < SCAN_ITEMS; i++) {
        int k = tid * SCAN_ITEMS + i;
        int c = (k < KBINS) ? g_C[k] : 0;
        loc[i] = run;
        run += c;
    }
    s[tid] = run;
    __syncthreads();
    for (int o = 1; o < 1024; o <<= 1) {
        int v = (tid >= o) ? s[tid - o] : 0;
        __syncthreads();
        s[tid] += v;
        __syncthreads();
    }
    int excl = tid ? s[tid - 1] : 0;
#pragma unroll
    for (int i = 0; i < SCAN_ITEMS; i++) {
        int k = tid * SCAN_ITEMS + i;
        if (k < KBINS) {
            int S = excl + loc[i];
            g_Sarr[k] = S;
            g_off[k]  = N - 2 * S - g_C[k];
        }
    }
}

// O[g][k] = S[k] + sum over blocks of groups g' < g of H[b'][k]  (GRP=4 blocks/group)
// Tiled transpose with one WARP per bin column (32 warps), staged through
// padded dynamic smem so global reads/writes are coalesced.
__global__ void __launch_bounds__(1024) k_blockoff() {
    extern __shared__ int tile[];   // NBG * 33 ints
    int k0 = blockIdx.x * 32;
    // stage group sums: each thread sums GRP consecutive-block H16s (coalesced per b-row)
    for (int idx = threadIdx.x; idx < NBG * 32; idx += 1024) {
        int g = idx >> 5, c = idx & 31;
        int k = k0 + c;
        int sum = 0;
        if (k < KBINS) {
#pragma unroll
            for (int q = 0; q < GRP; q++)
                sum += (int)g_H16[(g * GRP + q) * KBINS + k];
        }
        tile[g * 33 + c] = sum;
    }
    __syncthreads();
    int c = threadIdx.x >> 5;        // warp id == column
    int lane = threadIdx.x & 31;
    int k = k0 + c;
    if (k < KBINS) {
        int carry = g_Sarr[k];
#pragma unroll
        for (int t = 0; t < BOT; t++) {
            int g = t * 32 + lane;
            int v = (g < NBG) ? tile[g * 33 + c] : 0;
            int x = v;
#pragma unroll
            for (int o = 1; o < 32; o <<= 1) {
                int y = __shfl_up_sync(0xffffffffu, x, o);
                if (lane >= o) x += y;
            }
            if (g < NBG) tile[g * 33 + c] = carry + x - v;  // exclusive + S
            carry += __shfl_sync(0xffffffffu, x, 31);
        }
    }
    __syncthreads();
    for (int idx = threadIdx.x; idx < NBG * 32; idx += 1024) {
        int g = idx >> 5, c2 = idx & 31;
        int k2 = k0 + c2;
        if (k2 < KBINS) g_O[g * KBINS + k2] = tile[g * 33 + c2];
    }
}

// Fused stable-rank + scatter. Warps hand off via a named-barrier ring
// (producer bar.arrive -> consumer bar.sync). Single active warp in the
// critical section => plain LDS/STS RMW by match leaders (no atomics).
// Offset init: group base + residual per-block histograms.
__global__ void __launch_bounds__(FNT, 2)
k_fused(const int* __restrict__ dur, const float* __restrict__ lh,
        const int* __restrict__ ev, int N, int CH) {
    __shared__ int s_cnt[KBINS + 1];   // running global asc positions (+ sentinel)
    int tid = threadIdx.x, wid = tid >> 5, lane = tid & 31;
    unsigned lt = (1u << lane) - 1u;
    int b = blockIdx.x;
    int bg = b >> 2, rres = b & 3;
    for (int k = tid; k < KBINS; k += FNT) {
        int base = g_O[bg * KBINS + k];
#pragma unroll
        for (int q = 0; q < 3; q++)
            if (q < rres) base += (int)g_H16[(bg * GRP + q) * KBINS + k];
        s_cnt[k] = base;
    }
    if (tid == 0) s_cnt[KBINS] = 0;
    __syncthreads();

    int start = b * CH, end = min(start + CH, N);
    int tl = 0;
    for (int t0 = start; t0 < end; t0 += FTILE, tl++) {
        int key[EPT]; unsigned px[EPT]; int idx0 = t0 + wid * (EPT * 32) + lane;
        // ---- prefetch + compute outside critical section ----
#pragma unroll
        for (int m = 0; m < EPT; m++) {
            int i = idx0 + m * 32;
            bool v = (i < end);
            key[m] = v ? dur[i] : KBINS;
            float lhv = v ? lh[i] : 0.f;
            int evv = v ? (ev[i] & 1) : 0;
            px[m] = (__float_as_uint(__expf(lhv)) & 0xFFFFFFFEu) | (unsigned)evv;
        }
        // ---- wait for our turn: turn g = tl*8 + wid ----
        int par = tl & 1;
        if (tl + wid > 0) BAR_SYNC(wid + 8 * par);
        // ---- serialized ranking (plain smem RMW, single active warp) ----
        int j[EPT];
#pragma unroll
        for (int m = 0; m < EPT; m++) {
            unsigned mask = __match_any_sync(0xffffffffu, key[m]);
            int base = s_cnt[key[m]];                     // smem broadcast per group
            if (lane == (__ffs(mask) - 1))                // leader: distinct addr per group
                s_cnt[key[m]] = base + __popc(mask);
            j[m] = base + __popc(mask & lt);
        }
        // ---- hand off to next turn ----
        {
            int nw  = (wid + 1) & 7;
            int ntl = tl + (wid == 7);
            BAR_ARRIVE(nw + 8 * (ntl & 1));
        }
        // ---- scatter outside critical section ----
#pragma unroll
        for (int m = 0; m < EPT; m++) {
            if (key[m] < KBINS) {
                int pd = j[m] + __ldg(g_off + key[m]);
                g_expg2[pd] = px[m];
            }
        }
    }
}

// Per-bin contiguous segment reduction over DESC ranges (no atomics):
// bin k occupies desc positions [N-S-C, N-S).
__global__ void k_segseg(int N) {
    int w = (blockIdx.x * blockDim.x + threadIdx.x) >> 5;
    int lane = threadIdx.x & 31;
    if (w >= KBINS) return;
    int S = g_Sarr[w], C = g_C[w];
    int p0 = N - S - C;
    float se = 0.f; int cv = 0;
    for (int r = lane; r < C; r += 32) {
        unsigned x = __ldg(g_expg2 + p0 + r);
        se += __uint_as_float(x & 0xFFFFFFFEu);
        cv += (int)(x & 1u);
    }
    for (int o = 16; o; o >>= 1) {
        se += __shfl_down_sync(0xffffffffu, se, o);
        cv += __shfl_down_sync(0xffffffffu, cv, o);
    }
    if (lane == 0) { g_expg_sum[w] = se; g_ev_sum[w] = (float)cv; }
}

// base[k] = ev_sum / reverse-cumsum(expg_sum); totE; reset mse
__global__ void k_base() {
    __shared__ float s[1024];
    __shared__ float s2[32];
    int tid = threadIdx.x;
    float loc[SCAN_ITEMS];
    float run = 0.f, evt = 0.f;
#pragma unroll
    for (int i = 0; i < SCAN_ITEMS; i++) {
        int m = tid * SCAN_ITEMS + i;
        int k = KBINS - 1 - m;
        float v = (k >= 0) ? g_expg_sum[k] : 0.f;
        if (k >= 0) evt += g_ev_sum[k];
        run += v;
        loc[i] = run;
    }
    s[tid] = run;
    __syncthreads();
    for (int o = 1; o < 1024; o <<= 1) {
        float v = (tid >= o) ? s[tid - o] : 0.f;
        __syncthreads();
        s[tid] += v;
        __syncthreads();
    }
    float excl = tid ? s[tid - 1] : 0.f;
#pragma unroll
    for (int i = 0; i < SCAN_ITEMS; i++) {
        int m = tid * SCAN_ITEMS + i;
        int k = KBINS - 1 - m;
        if (k >= 0) {
            float risk = excl + loc[i];
            g_base[k] = (risk > 0.f) ? (g_ev_sum[k] / risk) : 0.f;
        }
    }
    for (int o = 16; o; o >>= 1) evt += __shfl_down_sync(0xffffffffu, evt, o);
    if ((tid & 31) == 0) s2[tid >> 5] = evt;
    __syncthreads();
    if (tid < 32) {
        float v = s2[tid];
        for (int o = 16; o; o >>= 1) v += __shfl_down_sync(0xffffffffu, v, o);
        if (tid == 0) { g_totE = v; g_mse = 0.0; }
    }
}

// Per-bin MSE over contiguous ASC ranges: for asc rank j = S+r of bin k,
// term = base[k]*expval(expg2[j]) - ebit(expg2[j + off[k]]). Both streams
// are linear within the segment — no index arrays, no random gathers.
__global__ void k_mseseg(int N) {
    int w = (blockIdx.x * blockDim.x + threadIdx.x) >> 5;
    int lane = threadIdx.x & 31;
    __shared__ double sd[32];
    double wacc = 0.0;
    if (w < KBINS) {
        int S = g_Sarr[w], C = g_C[w], off = g_off[w];
        float bv = g_base[w];
        float acc = 0.f;
        for (int r = lane; r < C; r += 32) {
            unsigned qa = __ldg(g_expg2 + S + r);
            unsigned qb = __ldg(g_expg2 + S + r + off);
            float t = bv * __uint_as_float(qa & 0xFFFFFFFEu) - (float)(qb & 1u);
            acc += t * t;
        }
        wacc = (double)acc;
    }
    for (int o = 16; o; o >>= 1) wacc += __shfl_down_sync(0xffffffffu, wacc, o);
    int wl = threadIdx.x >> 5;
    if (lane == 0) sd[wl] = wacc;
    __syncthreads();
    if (threadIdx.x < 32) {
        int nw = blockDim.x >> 5;
        double v = (threadIdx.x < nw) ? sd[threadIdx.x] : 0.0;
        for (int o = 16; o; o >>= 1) v += __shfl_down_sync(0xffffffffu, v, o);
        if (threadIdx.x == 0) atomicAdd(&g_mse, v);
    }
}

__global__ void k_fin(float* out, int N) {
    out[0] = (g_totE == 0.f) ? 0.f : (float)(g_mse / (double)N);
}

// ------------------------- host launcher ------------------------------------
extern "C" void kernel_launch(void* const* d_in, const int* in_sizes, int n_in,
                              void* d_out, int out_size) {
    const float* lh  = (const float*)d_in[0];
    const int*   dur = (const int*)d_in[1];
    const int*   ev  = (const int*)d_in[2];
    int N = in_sizes[0];
    float* out = (float*)d_out;
    int CH = (((N + NB - 1) / NB) + 3) & ~3;   // multiple of 4 -> int4-aligned chunks

    size_t bo_smem = (size_t)NBG * 33 * sizeof(int);
    cudaFuncSetAttribute(k_blockoff, cudaFuncAttributeMaxDynamicSharedMemorySize,
                         (int)bo_smem);

    k_zero<<<(KBINS + 1023) / 1024, 1024>>>();
    k_hist<<<NB, HNT>>>(dur, N, CH);
    k_scanC<<<1, 1024>>>(N);
    k_blockoff<<<(KBINS + 31) / 32, 1024, bo_smem>>>();
    k_fused<<<NB, FNT>>>(dur, lh, ev, N, CH);
    k_segseg<<<(KBINS * 32 + 255) / 256, 256>>>(N);
    k_base<<<1, 1024>>>();
    k_mseseg<<<(KBINS * 32 + 255) / 256, 256>>>(N);
    k_fin<<<1, 1>>>(out, N);
}